// round 10
// baseline (speedup 1.0000x reference)
#include <cuda_runtime.h>
#include <cuda_bf16.h>

typedef unsigned int u32;

#define BB 8192
#define TT 140
#define MROWS 32
#define THREADS 128

// smem byte offsets
// weights: 6 chunks x 8192B: W0hi W0lo W1i_hi W1i_lo W1h_hi W1h_lo
#define OFF_W    0
// h0: [parity][hi/lo] = 2 x (4096+4096) = 16384B ; h1 same
#define OFF_H0   49152
#define OFF_H1   (49152 + 16384)
#define SMEM_BYTES (OFF_H1 + 16384)

__device__ __forceinline__ u32 s2u(const void* p) {
    u32 a;
    asm("{ .reg .u64 t; cvta.to.shared.u64 t, %1; cvt.u32.u64 %0, t; }"
        : "=r"(a) : "l"(p));
    return a;
}
#define LDSM4(r0, r1, r2, r3, a)                                          \
    asm volatile("ldmatrix.sync.aligned.m8n8.x4.shared.b16 "              \
                 "{%0,%1,%2,%3}, [%4];"                                   \
                 : "=r"(r0), "=r"(r1), "=r"(r2), "=r"(r3) : "r"(a))

__device__ __forceinline__ void mma16816(float (&d)[4], u32 a0, u32 a1,
                                         u32 a2, u32 a3, u32 b0, u32 b1) {
    asm volatile(
        "mma.sync.aligned.m16n8k16.row.col.f32.bf16.bf16.f32 "
        "{%0,%1,%2,%3}, {%4,%5,%6,%7}, {%8,%9}, {%0,%1,%2,%3};"
        : "+f"(d[0]), "+f"(d[1]), "+f"(d[2]), "+f"(d[3])
        : "r"(a0), "r"(a1), "r"(a2), "r"(a3), "r"(b0), "r"(b1));
}
__device__ __forceinline__ u32 cvtpack(float hi, float lo) {  // {lo, hi} bf16x2
    u32 r;
    asm("cvt.rn.bf16x2.f32 %0, %1, %2;" : "=r"(r) : "f"(hi), "f"(lo));
    return r;
}
__device__ __forceinline__ float fast_tanh(float x) {
    float e = __expf(2.0f * x);
    return 1.0f - __fdividef(2.0f, e + 1.0f);
}
#define PAIRBAR(id) asm volatile("bar.sync %0, %1;" :: "r"(id), "r"(64) : "memory")

__global__ void __launch_bounds__(THREADS, 2) rnn_kernel(
    const float* __restrict__ x, const float* __restrict__ h_state,
    const float* __restrict__ Wih0, const float* __restrict__ Whh0,
    const float* __restrict__ bih0, const float* __restrict__ bhh0,
    const float* __restrict__ Wih1, const float* __restrict__ Whh1,
    const float* __restrict__ bih1, const float* __restrict__ bhh1,
    const float* __restrict__ Wout, const float* __restrict__ bout,
    float* __restrict__ out) {
    extern __shared__ char smem[];
    const int tid  = threadIdx.x;
    const int lane = tid & 31;
    const int w    = tid >> 5;
    const int role = w >> 1;        // 0 = layer-0 producer, 1 = layer-1 consumer
    const int wi   = w & 1;         // pair index (2 pairs per CTA)
    const int g    = lane >> 2;
    const int tg   = lane & 3;
    const int wr0  = wi * 16;       // pair's 16 CTA-local rows
    const int row0 = blockIdx.x * MROWS;
    const int bid  = 1 + wi;        // named barrier per pair (per-CTA resource)

    // ---- prologue: weights -> bf16 hi/lo, SW128-swizzled [j][k] ----
    {
        const float* Ws[3] = {Whh0, Wih1, Whh1};
        for (int idx = tid; idx < 3 * 4096; idx += THREADS) {
            int m = idx >> 12, e = idx & 4095, j = e >> 6, k = e & 63;
            float v = Ws[m][j * 64 + k];
            __nv_bfloat16 hb = __float2bfloat16(v);
            __nv_bfloat16 lb = __float2bfloat16(v - __bfloat162float(hb));
            int sw = j * 128 + ((k * 2) ^ ((j & 7) << 4));
            *(__nv_bfloat16*)(smem + OFF_W + (2 * m) * 8192 + sw)     = hb;
            *(__nv_bfloat16*)(smem + OFF_W + (2 * m + 1) * 8192 + sw) = lb;
        }
    }
    // h_state -> parity-0 buffers (hi at +0, lo at +4096)
    for (int idx = tid; idx < MROWS * 64; idx += THREADS) {
        int r = idx >> 6, k = idx & 63;
        int sw = r * 128 + ((k * 2) ^ ((r & 7) << 4));
        float v0 = h_state[(row0 + r) * 64 + k];
        float v1 = h_state[BB * 64 + (row0 + r) * 64 + k];
        __nv_bfloat16 h0h = __float2bfloat16(v0);
        __nv_bfloat16 h1h = __float2bfloat16(v1);
        *(__nv_bfloat16*)(smem + OFF_H0 + sw)        = h0h;
        *(__nv_bfloat16*)(smem + OFF_H0 + 4096 + sw) = __float2bfloat16(v0 - __bfloat162float(h0h));
        *(__nv_bfloat16*)(smem + OFF_H1 + sw)        = h1h;
        *(__nv_bfloat16*)(smem + OFF_H1 + 4096 + sw) = __float2bfloat16(v1 - __bfloat162float(h1h));
    }
    // per-lane constants: cols j = nt*8 + tg*2, +1
    float2 wi2[8], b02[8], b12[8], wo2[8];
#pragma unroll
    for (int nt = 0; nt < 8; ++nt) {
        int j = nt * 8 + tg * 2;
        wi2[nt] = make_float2(Wih0[j], Wih0[j + 1]);
        b02[nt] = make_float2(bih0[j] + bhh0[j], bih0[j + 1] + bhh0[j + 1]);
        b12[nt] = make_float2(bih1[j] + bhh1[j], bih1[j + 1] + bhh1[j + 1]);
        wo2[nt] = make_float2(Wout[j], Wout[j + 1]);
    }
    const float bo = bout[0];
    __syncthreads();

    const u32 smu = s2u(smem);
    // A-operand (rows) ldmatrix addressing
    const int q    = lane >> 3;
    const int arow = wr0 + ((q & 1) << 3) + (lane & 7);
    const u32 aco  = (u32)((q >> 1) << 4);
    const u32 swz  = (u32)((lane & 7) << 4);
    const u32 ab0  = smu + OFF_H0 + arow * 128;   // + parity*8192 (+4096 for lo)
    const u32 ab1  = smu + OFF_H1 + arow * 128;
    // B-operand (weights) ldmatrix addressing
    const int brl  = (((lane >> 4) & 1) << 3) + (lane & 7);
    const u32 bco  = (u32)(((lane >> 3) & 1) << 4);
    const u32 bbase = smu + OFF_W + brl * 128;
    // h store addresses (per nt; add parity*8192 / +4096 for lo at use)
    u32 st0[8], st1[8];
#pragma unroll
    for (int nt = 0; nt < 8; ++nt) {
        u32 c = (u32)((nt * 16 + tg * 4) ^ (g << 4));
        st0[nt] = smu + OFF_H0 + (wr0 + g) * 128 + c;
        st1[nt] = smu + OFF_H1 + (wr0 + g) * 128 + c;
    }

    if (role == 0) {
        // ================= producer: layer 0 =================
        const float* gxA = x + (row0 + wr0 + g) * TT;
        const float* gxB = gxA + 8 * TT;
        float xAn = gxA[0], xBn = gxB[0];
        u32 p = 0;
        for (int t = 0; t < TT; ++t) {
            const u32 rdo = p * 8192u, wro = rdo ^ 8192u;
            float xA = xAn, xB = xBn;
            int tn = (t + 1 < TT) ? t + 1 : TT - 1;
            xAn = gxA[tn]; xBn = gxB[tn];

            float acc[8][4];
#pragma unroll
            for (int n = 0; n < 8; ++n)
#pragma unroll
                for (int i = 0; i < 4; ++i) acc[n][i] = 0.0f;
#pragma unroll
            for (int kt = 0; kt < 4; ++kt) {
                u32 kc = (u32)(kt << 5);
                u32 aoff = (kc | aco) ^ swz;
                u32 aH0, aH1, aH2, aH3, aL0, aL1, aL2, aL3;
                LDSM4(aH0, aH1, aH2, aH3, ab0 + rdo + aoff);
                LDSM4(aL0, aL1, aL2, aL3, ab0 + rdo + 4096 + aoff);
                u32 boff = (kc | bco) ^ swz;
#pragma unroll
                for (int np = 0; np < 4; ++np) {
                    u32 bb = bbase + np * 2048 + boff;
                    u32 h0, h1, h2, h3, l0, l1, l2, l3;
                    LDSM4(h0, h1, h2, h3, bb);            // W0 hi
                    LDSM4(l0, l1, l2, l3, bb + 8192);     // W0 lo
                    mma16816(acc[2 * np],     aH0, aH1, aH2, aH3, h0, h1);
                    mma16816(acc[2 * np + 1], aH0, aH1, aH2, aH3, h2, h3);
                    mma16816(acc[2 * np],     aL0, aL1, aL2, aL3, h0, h1);
                    mma16816(acc[2 * np + 1], aL0, aL1, aL2, aL3, h2, h3);
                    mma16816(acc[2 * np],     aH0, aH1, aH2, aH3, l0, l1);
                    mma16816(acc[2 * np + 1], aH0, aH1, aH2, aH3, l2, l3);
                }
            }
            u32 hpA[8], lpA[8], hpB[8], lpB[8];
#pragma unroll
            for (int nt = 0; nt < 8; ++nt) {
                float vA0 = fast_tanh(acc[nt][0] + fmaf(xA, wi2[nt].x, b02[nt].x));
                float vA1 = fast_tanh(acc[nt][1] + fmaf(xA, wi2[nt].y, b02[nt].y));
                float vB0 = fast_tanh(acc[nt][2] + fmaf(xB, wi2[nt].x, b02[nt].x));
                float vB1 = fast_tanh(acc[nt][3] + fmaf(xB, wi2[nt].y, b02[nt].y));
                u32 hA = cvtpack(vA1, vA0), hB = cvtpack(vB1, vB0);
                float aLo = __uint_as_float(hA << 16);
                float aHi = __uint_as_float(hA & 0xFFFF0000u);
                float bLo = __uint_as_float(hB << 16);
                float bHi = __uint_as_float(hB & 0xFFFF0000u);
                hpA[nt] = hA; hpB[nt] = hB;
                lpA[nt] = cvtpack(vA1 - aHi, vA0 - aLo);
                lpB[nt] = cvtpack(vB1 - bHi, vB0 - bLo);
            }
#pragma unroll
            for (int nt = 0; nt < 8; ++nt) {
                asm volatile("st.shared.b32 [%0], %1;" :: "r"(st0[nt] + wro), "r"(hpA[nt]));
                asm volatile("st.shared.b32 [%0], %1;" :: "r"(st0[nt] + wro + 1024), "r"(hpB[nt]));
                asm volatile("st.shared.b32 [%0], %1;" :: "r"(st0[nt] + wro + 4096), "r"(lpA[nt]));
                asm volatile("st.shared.b32 [%0], %1;" :: "r"(st0[nt] + wro + 4096 + 1024), "r"(lpB[nt]));
            }
            PAIRBAR(bid);   // publish h0n(t) to consumer
            p ^= 1;
        }
    } else {
        // ================= consumer: layer 1 =================
        float* outy = out + (row0 + wr0 + g) * TT;
        u32 p = 0;
        for (int t = 0; t < TT; ++t) {
            const u32 rdo = p * 8192u, wro = rdo ^ 8192u;
            float acc[8][4];
#pragma unroll
            for (int n = 0; n < 8; ++n)
#pragma unroll
                for (int i = 0; i < 4; ++i) acc[n][i] = 0.0f;
            // part 1 (pre-barrier): Whh1 x h1(t-1) — consumer-private
#pragma unroll
            for (int kt = 0; kt < 4; ++kt) {
                u32 kc = (u32)(kt << 5);
                u32 aoff = (kc | aco) ^ swz;
                u32 r0, r1, r2, r3, s0, s1, s2, s3;
                LDSM4(r0, r1, r2, r3, ab1 + rdo + aoff);
                LDSM4(s0, s1, s2, s3, ab1 + rdo + 4096 + aoff);
                u32 boff = (kc | bco) ^ swz;
#pragma unroll
                for (int np = 0; np < 4; ++np) {
                    u32 bb = bbase + np * 2048 + boff;
                    u32 hh0, hh1, hh2, hh3, hl0, hl1, hl2, hl3;
                    LDSM4(hh0, hh1, hh2, hh3, bb + 32768);   // W1h hi
                    LDSM4(hl0, hl1, hl2, hl3, bb + 40960);   // W1h lo
                    mma16816(acc[2 * np],     r0, r1, r2, r3, hh0, hh1);
                    mma16816(acc[2 * np + 1], r0, r1, r2, r3, hh2, hh3);
                    mma16816(acc[2 * np],     s0, s1, s2, s3, hh0, hh1);
                    mma16816(acc[2 * np + 1], s0, s1, s2, s3, hh2, hh3);
                    mma16816(acc[2 * np],     r0, r1, r2, r3, hl0, hl1);
                    mma16816(acc[2 * np + 1], r0, r1, r2, r3, hl2, hl3);
                }
            }
            PAIRBAR(bid);   // wait for producer's h0n(t)
            // part 2: Wih1 x h0n(t)  (h0n lives at parity wro)
#pragma unroll
            for (int kt = 0; kt < 4; ++kt) {
                u32 kc = (u32)(kt << 5);
                u32 aoff = (kc | aco) ^ swz;
                u32 p0, p1, p2, p3, q0, q1, q2, q3;
                LDSM4(p0, p1, p2, p3, ab0 + wro + aoff);
                LDSM4(q0, q1, q2, q3, ab0 + wro + 4096 + aoff);
                u32 boff = (kc | bco) ^ swz;
#pragma unroll
                for (int np = 0; np < 4; ++np) {
                    u32 bb = bbase + np * 2048 + boff;
                    u32 ih0, ih1, ih2, ih3, il0, il1, il2, il3;
                    LDSM4(ih0, ih1, ih2, ih3, bb + 16384);   // W1i hi
                    LDSM4(il0, il1, il2, il3, bb + 24576);   // W1i lo
                    mma16816(acc[2 * np],     p0, p1, p2, p3, ih0, ih1);
                    mma16816(acc[2 * np + 1], p0, p1, p2, p3, ih2, ih3);
                    mma16816(acc[2 * np],     q0, q1, q2, q3, ih0, ih1);
                    mma16816(acc[2 * np + 1], q0, q1, q2, q3, ih2, ih3);
                    mma16816(acc[2 * np],     p0, p1, p2, p3, il0, il1);
                    mma16816(acc[2 * np + 1], p0, p1, p2, p3, il2, il3);
                }
            }
            float ypA = 0.0f, ypB = 0.0f;
            u32 hpA[8], lpA[8], hpB[8], lpB[8];
#pragma unroll
            for (int nt = 0; nt < 8; ++nt) {
                float vA0 = fast_tanh(acc[nt][0] + b12[nt].x);
                float vA1 = fast_tanh(acc[nt][1] + b12[nt].y);
                float vB0 = fast_tanh(acc[nt][2] + b12[nt].x);
                float vB1 = fast_tanh(acc[nt][3] + b12[nt].y);
                ypA = fmaf(vA0, wo2[nt].x, ypA); ypA = fmaf(vA1, wo2[nt].y, ypA);
                ypB = fmaf(vB0, wo2[nt].x, ypB); ypB = fmaf(vB1, wo2[nt].y, ypB);
                u32 hA = cvtpack(vA1, vA0), hB = cvtpack(vB1, vB0);
                float aLo = __uint_as_float(hA << 16);
                float aHi = __uint_as_float(hA & 0xFFFF0000u);
                float bLo = __uint_as_float(hB << 16);
                float bHi = __uint_as_float(hB & 0xFFFF0000u);
                hpA[nt] = hA; hpB[nt] = hB;
                lpA[nt] = cvtpack(vA1 - aHi, vA0 - aLo);
                lpB[nt] = cvtpack(vB1 - bHi, vB0 - bLo);
            }
#pragma unroll
            for (int nt = 0; nt < 8; ++nt) {
                asm volatile("st.shared.b32 [%0], %1;" :: "r"(st1[nt] + wro), "r"(hpA[nt]));
                asm volatile("st.shared.b32 [%0], %1;" :: "r"(st1[nt] + wro + 1024), "r"(hpB[nt]));
                asm volatile("st.shared.b32 [%0], %1;" :: "r"(st1[nt] + wro + 4096), "r"(lpA[nt]));
                asm volatile("st.shared.b32 [%0], %1;" :: "r"(st1[nt] + wro + 4096 + 1024), "r"(lpB[nt]));
            }
            // y reduce over tg
            ypA += __shfl_xor_sync(0xFFFFFFFF, ypA, 1);
            ypA += __shfl_xor_sync(0xFFFFFFFF, ypA, 2);
            ypB += __shfl_xor_sync(0xFFFFFFFF, ypB, 1);
            ypB += __shfl_xor_sync(0xFFFFFFFF, ypB, 2);
            if (tg == 0) {
                outy[t]          = ypA + bo;
                outy[8 * TT + t] = ypB + bo;
            }
            __syncwarp();
            p ^= 1;
        }
    }
    __syncthreads();

    // ---- h_final from hi+lo (final state in parity 0: TT even) ----
    const int BT = BB * TT;
    for (int idx = tid; idx < MROWS * 64; idx += THREADS) {
        int r = idx >> 6, k = idx & 63;
        int sw = r * 128 + ((k * 2) ^ ((r & 7) << 4));
        float h0 = __bfloat162float(*(__nv_bfloat16*)(smem + OFF_H0 + sw)) +
                   __bfloat162float(*(__nv_bfloat16*)(smem + OFF_H0 + 4096 + sw));
        float h1 = __bfloat162float(*(__nv_bfloat16*)(smem + OFF_H1 + sw)) +
                   __bfloat162float(*(__nv_bfloat16*)(smem + OFF_H1 + 4096 + sw));
        out[BT + (row0 + r) * 64 + k]           = h0;
        out[BT + BB * 64 + (row0 + r) * 64 + k] = h1;
    }
}

extern "C" void kernel_launch(void* const* d_in, const int* in_sizes, int n_in,
                              void* d_out, int out_size) {
    (void)in_sizes; (void)n_in; (void)out_size;
    const float* x    = (const float*)d_in[0];
    const float* hs   = (const float*)d_in[1];
    const float* Wih0 = (const float*)d_in[2];
    const float* Whh0 = (const float*)d_in[3];
    const float* bih0 = (const float*)d_in[4];
    const float* bhh0 = (const float*)d_in[5];
    const float* Wih1 = (const float*)d_in[6];
    const float* Whh1 = (const float*)d_in[7];
    const float* bih1 = (const float*)d_in[8];
    const float* bhh1 = (const float*)d_in[9];
    const float* Wout = (const float*)d_in[10];
    const float* bout = (const float*)d_in[11];
    float* out = (float*)d_out;

    cudaFuncSetAttribute(rnn_kernel, cudaFuncAttributeMaxDynamicSharedMemorySize,
                         SMEM_BYTES);
    rnn_kernel<<<BB / MROWS, THREADS, SMEM_BYTES>>>(
        x, hs, Wih0, Whh0, bih0, bhh0, Wih1, Whh1, bih1, bhh1, Wout, bout, out);
}

// round 11
// speedup vs baseline: 1.2948x; 1.2948x over previous
#include <cuda_runtime.h>
#include <cuda_bf16.h>

typedef unsigned int u32;

#define BB 8192
#define TT 140
#define MROWS 64
#define THREADS 512

// smem byte offsets
// weights: 6 chunks x 8192B: W0hi W0lo W1i_hi W1i_lo W1h_hi W1h_lo
#define OFF_W    0
// h0: [parity][hi/lo] = 4 x 8192B ; h1 same
#define OFF_H0   49152
#define OFF_H1   (49152 + 32768)
#define OFF_YP   (OFF_H1 + 32768)       // ypart[pair][half][16] floats = 512B
#define SMEM_BYTES (OFF_YP + 512)

__device__ __forceinline__ u32 s2u(const void* p) {
    u32 a;
    asm("{ .reg .u64 t; cvta.to.shared.u64 t, %1; cvt.u32.u64 %0, t; }"
        : "=r"(a) : "l"(p));
    return a;
}
#define LDSM4(r0, r1, r2, r3, a)                                          \
    asm volatile("ldmatrix.sync.aligned.m8n8.x4.shared.b16 "              \
                 "{%0,%1,%2,%3}, [%4];"                                   \
                 : "=r"(r0), "=r"(r1), "=r"(r2), "=r"(r3) : "r"(a))

__device__ __forceinline__ void mma16816(float (&d)[4], u32 a0, u32 a1,
                                         u32 a2, u32 a3, u32 b0, u32 b1) {
    asm volatile(
        "mma.sync.aligned.m16n8k16.row.col.f32.bf16.bf16.f32 "
        "{%0,%1,%2,%3}, {%4,%5,%6,%7}, {%8,%9}, {%0,%1,%2,%3};"
        : "+f"(d[0]), "+f"(d[1]), "+f"(d[2]), "+f"(d[3])
        : "r"(a0), "r"(a1), "r"(a2), "r"(a3), "r"(b0), "r"(b1));
}
__device__ __forceinline__ u32 cvtpack(float hi, float lo) {  // {lo, hi} bf16x2
    u32 r;
    asm("cvt.rn.bf16x2.f32 %0, %1, %2;" : "=r"(r) : "f"(hi), "f"(lo));
    return r;
}
__device__ __forceinline__ float fast_tanh(float x) {
    float e = __expf(2.0f * x);
    return 1.0f - __fdividef(2.0f, e + 1.0f);
}
#define PAIRBAR(id) asm volatile("bar.sync %0, %1;" :: "r"(id), "r"(128) : "memory")
#define CONSBAR(id) asm volatile("bar.sync %0, %1;" :: "r"(id), "r"(64) : "memory")

__global__ void __launch_bounds__(THREADS, 1) rnn_kernel(
    const float* __restrict__ x, const float* __restrict__ h_state,
    const float* __restrict__ Wih0, const float* __restrict__ Whh0,
    const float* __restrict__ bih0, const float* __restrict__ bhh0,
    const float* __restrict__ Wih1, const float* __restrict__ Whh1,
    const float* __restrict__ bih1, const float* __restrict__ bhh1,
    const float* __restrict__ Wout, const float* __restrict__ bout,
    float* __restrict__ out) {
    extern __shared__ char smem[];
    const int tid  = threadIdx.x;
    const int lane = tid & 31;
    const int w    = tid >> 5;
    const int role = w >> 3;            // 0 = producer (layer 0), 1 = consumer (layer 1)
    const int hf   = (w >> 2) & 1;      // j-column half: 0 -> j 0..31, 1 -> j 32..63
    // SMSP s hosts producers of pair s (both halves) + consumers of pair s-1.
    const int wi   = (role == 0) ? (w & 3) : ((w + 3) & 3);
    const int g    = lane >> 2;
    const int tg   = lane & 3;
    const int wr0  = wi * 16;           // pair's 16 CTA-local rows
    const int row0 = blockIdx.x * MROWS;
    const int bidP = 1 + wi;            // 128-thread pair barrier
    const int bidC = 5 + wi;            // 64-thread consumer barrier

    // ---- prologue: weights -> bf16 hi/lo, SW128-swizzled [j][k] ----
    {
        const float* Ws[3] = {Whh0, Wih1, Whh1};
        for (int idx = tid; idx < 3 * 4096; idx += THREADS) {
            int m = idx >> 12, e = idx & 4095, j = e >> 6, k = e & 63;
            float v = Ws[m][j * 64 + k];
            __nv_bfloat16 hb = __float2bfloat16(v);
            __nv_bfloat16 lb = __float2bfloat16(v - __bfloat162float(hb));
            int sw = j * 128 + ((k * 2) ^ ((j & 7) << 4));
            *(__nv_bfloat16*)(smem + OFF_W + (2 * m) * 8192 + sw)     = hb;
            *(__nv_bfloat16*)(smem + OFF_W + (2 * m + 1) * 8192 + sw) = lb;
        }
    }
    // h_state -> parity-0 buffers
    for (int idx = tid; idx < MROWS * 64; idx += THREADS) {
        int r = idx >> 6, k = idx & 63;
        int sw = r * 128 + ((k * 2) ^ ((r & 7) << 4));
        float v0 = h_state[(row0 + r) * 64 + k];
        float v1 = h_state[BB * 64 + (row0 + r) * 64 + k];
        __nv_bfloat16 h0h = __float2bfloat16(v0);
        __nv_bfloat16 h1h = __float2bfloat16(v1);
        *(__nv_bfloat16*)(smem + OFF_H0 + sw)        = h0h;
        *(__nv_bfloat16*)(smem + OFF_H0 + 8192 + sw) = __float2bfloat16(v0 - __bfloat162float(h0h));
        *(__nv_bfloat16*)(smem + OFF_H1 + sw)        = h1h;
        *(__nv_bfloat16*)(smem + OFF_H1 + 8192 + sw) = __float2bfloat16(v1 - __bfloat162float(h1h));
    }
    // per-lane constants: cols j = hf*32 + nt*8 + tg*2, +1
    float2 wi2[4], b02[4], b12[4], wo2[4];
#pragma unroll
    for (int nt = 0; nt < 4; ++nt) {
        int j = hf * 32 + nt * 8 + tg * 2;
        wi2[nt] = make_float2(Wih0[j], Wih0[j + 1]);
        b02[nt] = make_float2(bih0[j] + bhh0[j], bih0[j + 1] + bhh0[j + 1]);
        b12[nt] = make_float2(bih1[j] + bhh1[j], bih1[j + 1] + bhh1[j + 1]);
        wo2[nt] = make_float2(Wout[j], Wout[j + 1]);
    }
    const float bo = bout[0];
    __syncthreads();

    const u32 smu = s2u(smem);
    // A-operand (rows) ldmatrix addressing
    const int q    = lane >> 3;
    const int arow = wr0 + ((q & 1) << 3) + (lane & 7);
    const u32 aco  = (u32)((q >> 1) << 4);
    const u32 swz  = (u32)((lane & 7) << 4);
    const u32 ab0  = smu + OFF_H0 + arow * 128;   // + parity*16384 (+8192 for lo)
    const u32 ab1  = smu + OFF_H1 + arow * 128;
    // B-operand (weights) ldmatrix addressing
    const int brl  = (((lane >> 4) & 1) << 3) + (lane & 7);
    const u32 bco  = (u32)(((lane >> 3) & 1) << 4);
    const u32 bbase = smu + OFF_W + brl * 128;
    // h store addresses (j-half hf; add parity*16384 / +8192 for lo at use)
    u32 st0[4], st1[4];
#pragma unroll
    for (int nt = 0; nt < 4; ++nt) {
        u32 c = (u32)((hf * 64 + nt * 16 + tg * 4) ^ (g << 4));
        st0[nt] = smu + OFF_H0 + (wr0 + g) * 128 + c;
        st1[nt] = smu + OFF_H1 + (wr0 + g) * 128 + c;
    }
    float* yprt = (float*)(smem + OFF_YP) + wi * 32;   // [half][16]

    if (role == 0) {
        // ================= producer: layer 0, j-half hf =================
        const float* gxA = x + (row0 + wr0 + g) * TT;
        const float* gxB = gxA + 8 * TT;
        float xAn = gxA[0], xBn = gxB[0];
        u32 p = 0;
        for (int t = 0; t < TT; ++t) {
            const u32 rdo = p * 16384u, wro = rdo ^ 16384u;
            float xA = xAn, xB = xBn;
            int tn = (t + 1 < TT) ? t + 1 : TT - 1;
            xAn = gxA[tn]; xBn = gxB[tn];

            float acc[4][4];
#pragma unroll
            for (int n = 0; n < 4; ++n)
#pragma unroll
                for (int i = 0; i < 4; ++i) acc[n][i] = 0.0f;
#pragma unroll
            for (int kt = 0; kt < 4; ++kt) {
                u32 kc = (u32)(kt << 5);
                u32 aoff = (kc | aco) ^ swz;
                u32 aH0, aH1, aH2, aH3, aL0, aL1, aL2, aL3;
                LDSM4(aH0, aH1, aH2, aH3, ab0 + rdo + aoff);
                LDSM4(aL0, aL1, aL2, aL3, ab0 + rdo + 8192 + aoff);
                u32 boff = (kc | bco) ^ swz;
#pragma unroll
                for (int np = 0; np < 2; ++np) {
                    u32 bb = bbase + (u32)((hf * 2 + np) * 2048) + boff;
                    u32 h0, h1, h2, h3, l0, l1, l2, l3;
                    LDSM4(h0, h1, h2, h3, bb);            // W0 hi
                    LDSM4(l0, l1, l2, l3, bb + 8192);     // W0 lo
                    mma16816(acc[2 * np],     aH0, aH1, aH2, aH3, h0, h1);
                    mma16816(acc[2 * np + 1], aH0, aH1, aH2, aH3, h2, h3);
                    mma16816(acc[2 * np],     aL0, aL1, aL2, aL3, h0, h1);
                    mma16816(acc[2 * np + 1], aL0, aL1, aL2, aL3, h2, h3);
                    mma16816(acc[2 * np],     aH0, aH1, aH2, aH3, l0, l1);
                    mma16816(acc[2 * np + 1], aH0, aH1, aH2, aH3, l2, l3);
                }
            }
            u32 hpA[4], lpA[4], hpB[4], lpB[4];
#pragma unroll
            for (int nt = 0; nt < 4; ++nt) {
                float vA0 = fast_tanh(acc[nt][0] + fmaf(xA, wi2[nt].x, b02[nt].x));
                float vA1 = fast_tanh(acc[nt][1] + fmaf(xA, wi2[nt].y, b02[nt].y));
                float vB0 = fast_tanh(acc[nt][2] + fmaf(xB, wi2[nt].x, b02[nt].x));
                float vB1 = fast_tanh(acc[nt][3] + fmaf(xB, wi2[nt].y, b02[nt].y));
                u32 hA = cvtpack(vA1, vA0), hB = cvtpack(vB1, vB0);
                float aLo = __uint_as_float(hA << 16);
                float aHi = __uint_as_float(hA & 0xFFFF0000u);
                float bLo = __uint_as_float(hB << 16);
                float bHi = __uint_as_float(hB & 0xFFFF0000u);
                hpA[nt] = hA; hpB[nt] = hB;
                lpA[nt] = cvtpack(vA1 - aHi, vA0 - aLo);
                lpB[nt] = cvtpack(vB1 - bHi, vB0 - bLo);
            }
#pragma unroll
            for (int nt = 0; nt < 4; ++nt) {
                asm volatile("st.shared.b32 [%0], %1;" :: "r"(st0[nt] + wro), "r"(hpA[nt]));
                asm volatile("st.shared.b32 [%0], %1;" :: "r"(st0[nt] + wro + 1024), "r"(hpB[nt]));
                asm volatile("st.shared.b32 [%0], %1;" :: "r"(st0[nt] + wro + 8192), "r"(lpA[nt]));
                asm volatile("st.shared.b32 [%0], %1;" :: "r"(st0[nt] + wro + 8192 + 1024), "r"(lpB[nt]));
            }
            PAIRBAR(bidP);   // publish h0n(t) to pair
            p ^= 1;
        }
    } else {
        // ================= consumer: layer 1, j-half hf =================
        float* outy = out + (row0 + wr0 + g) * TT;
        u32 p = 0;
        for (int t = 0; t < TT; ++t) {
            const u32 rdo = p * 16384u, wro = rdo ^ 16384u;
            float acc[4][4];
#pragma unroll
            for (int n = 0; n < 4; ++n)
#pragma unroll
                for (int i = 0; i < 4; ++i) acc[n][i] = 0.0f;
            // part 1 (pre-pair-barrier): Whh1 x h1(t-1)
#pragma unroll
            for (int kt = 0; kt < 4; ++kt) {
                u32 kc = (u32)(kt << 5);
                u32 aoff = (kc | aco) ^ swz;
                u32 r0, r1, r2, r3, s0, s1, s2, s3;
                LDSM4(r0, r1, r2, r3, ab1 + rdo + aoff);
                LDSM4(s0, s1, s2, s3, ab1 + rdo + 8192 + aoff);
                u32 boff = (kc | bco) ^ swz;
#pragma unroll
                for (int np = 0; np < 2; ++np) {
                    u32 bb = bbase + (u32)((hf * 2 + np) * 2048) + boff;
                    u32 hh0, hh1, hh2, hh3, hl0, hl1, hl2, hl3;
                    LDSM4(hh0, hh1, hh2, hh3, bb + 32768);   // W1h hi
                    LDSM4(hl0, hl1, hl2, hl3, bb + 40960);   // W1h lo
                    mma16816(acc[2 * np],     r0, r1, r2, r3, hh0, hh1);
                    mma16816(acc[2 * np + 1], r0, r1, r2, r3, hh2, hh3);
                    mma16816(acc[2 * np],     s0, s1, s2, s3, hh0, hh1);
                    mma16816(acc[2 * np + 1], s0, s1, s2, s3, hh2, hh3);
                    mma16816(acc[2 * np],     r0, r1, r2, r3, hl0, hl1);
                    mma16816(acc[2 * np + 1], r0, r1, r2, r3, hl2, hl3);
                }
            }
            PAIRBAR(bidP);   // wait for producers' h0n(t)
            // part 2: Wih1 x h0n(t)  (h0n lives at parity wro)
#pragma unroll
            for (int kt = 0; kt < 4; ++kt) {
                u32 kc = (u32)(kt << 5);
                u32 aoff = (kc | aco) ^ swz;
                u32 p0, p1, p2, p3, q0, q1, q2, q3;
                LDSM4(p0, p1, p2, p3, ab0 + wro + aoff);
                LDSM4(q0, q1, q2, q3, ab0 + wro + 8192 + aoff);
                u32 boff = (kc | bco) ^ swz;
#pragma unroll
                for (int np = 0; np < 2; ++np) {
                    u32 bb = bbase + (u32)((hf * 2 + np) * 2048) + boff;
                    u32 ih0, ih1, ih2, ih3, il0, il1, il2, il3;
                    LDSM4(ih0, ih1, ih2, ih3, bb + 16384);   // W1i hi
                    LDSM4(il0, il1, il2, il3, bb + 24576);   // W1i lo
                    mma16816(acc[2 * np],     p0, p1, p2, p3, ih0, ih1);
                    mma16816(acc[2 * np + 1], p0, p1, p2, p3, ih2, ih3);
                    mma16816(acc[2 * np],     q0, q1, q2, q3, ih0, ih1);
                    mma16816(acc[2 * np + 1], q0, q1, q2, q3, ih2, ih3);
                    mma16816(acc[2 * np],     p0, p1, p2, p3, il0, il1);
                    mma16816(acc[2 * np + 1], p0, p1, p2, p3, il2, il3);
                }
            }
            float ypA = 0.0f, ypB = 0.0f;
            u32 hpA[4], lpA[4], hpB[4], lpB[4];
#pragma unroll
            for (int nt = 0; nt < 4; ++nt) {
                float vA0 = fast_tanh(acc[nt][0] + b12[nt].x);
                float vA1 = fast_tanh(acc[nt][1] + b12[nt].y);
                float vB0 = fast_tanh(acc[nt][2] + b12[nt].x);
                float vB1 = fast_tanh(acc[nt][3] + b12[nt].y);
                ypA = fmaf(vA0, wo2[nt].x, ypA); ypA = fmaf(vA1, wo2[nt].y, ypA);
                ypB = fmaf(vB0, wo2[nt].x, ypB); ypB = fmaf(vB1, wo2[nt].y, ypB);
                u32 hA = cvtpack(vA1, vA0), hB = cvtpack(vB1, vB0);
                float aLo = __uint_as_float(hA << 16);
                float aHi = __uint_as_float(hA & 0xFFFF0000u);
                float bLo = __uint_as_float(hB << 16);
                float bHi = __uint_as_float(hB & 0xFFFF0000u);
                hpA[nt] = hA; hpB[nt] = hB;
                lpA[nt] = cvtpack(vA1 - aHi, vA0 - aLo);
                lpB[nt] = cvtpack(vB1 - bHi, vB0 - bLo);
            }
#pragma unroll
            for (int nt = 0; nt < 4; ++nt) {
                asm volatile("st.shared.b32 [%0], %1;" :: "r"(st1[nt] + wro), "r"(hpA[nt]));
                asm volatile("st.shared.b32 [%0], %1;" :: "r"(st1[nt] + wro + 1024), "r"(hpB[nt]));
                asm volatile("st.shared.b32 [%0], %1;" :: "r"(st1[nt] + wro + 8192), "r"(lpA[nt]));
                asm volatile("st.shared.b32 [%0], %1;" :: "r"(st1[nt] + wro + 8192 + 1024), "r"(lpB[nt]));
            }
            // y partial: reduce over tg within warp, stash per half
            ypA += __shfl_xor_sync(0xFFFFFFFF, ypA, 1);
            ypA += __shfl_xor_sync(0xFFFFFFFF, ypA, 2);
            ypB += __shfl_xor_sync(0xFFFFFFFF, ypB, 1);
            ypB += __shfl_xor_sync(0xFFFFFFFF, ypB, 2);
            if (tg == 0) {
                yprt[hf * 16 + g]     = ypA;
                yprt[hf * 16 + g + 8] = ypB;
            }
            CONSBAR(bidC);   // h1n (both halves) + ypart visible to consumer pair
            if (hf == 0 && tg == 0) {
                outy[t]          = yprt[g]     + yprt[16 + g]     + bo;
                outy[8 * TT + t] = yprt[g + 8] + yprt[16 + g + 8] + bo;
            }
            p ^= 1;
        }
    }
    __syncthreads();

    // ---- h_final from hi+lo (final state in parity 0: TT even) ----
    const int BT = BB * TT;
    for (int idx = tid; idx < MROWS * 64; idx += THREADS) {
        int r = idx >> 6, k = idx & 63;
        int sw = r * 128 + ((k * 2) ^ ((r & 7) << 4));
        float h0 = __bfloat162float(*(__nv_bfloat16*)(smem + OFF_H0 + sw)) +
                   __bfloat162float(*(__nv_bfloat16*)(smem + OFF_H0 + 8192 + sw));
        float h1 = __bfloat162float(*(__nv_bfloat16*)(smem + OFF_H1 + sw)) +
                   __bfloat162float(*(__nv_bfloat16*)(smem + OFF_H1 + 8192 + sw));
        out[BT + (row0 + r) * 64 + k]           = h0;
        out[BT + BB * 64 + (row0 + r) * 64 + k] = h1;
    }
}

extern "C" void kernel_launch(void* const* d_in, const int* in_sizes, int n_in,
                              void* d_out, int out_size) {
    (void)in_sizes; (void)n_in; (void)out_size;
    const float* x    = (const float*)d_in[0];
    const float* hs   = (const float*)d_in[1];
    const float* Wih0 = (const float*)d_in[2];
    const float* Whh0 = (const float*)d_in[3];
    const float* bih0 = (const float*)d_in[4];
    const float* bhh0 = (const float*)d_in[5];
    const float* Wih1 = (const float*)d_in[6];
    const float* Whh1 = (const float*)d_in[7];
    const float* bih1 = (const float*)d_in[8];
    const float* bhh1 = (const float*)d_in[9];
    const float* Wout = (const float*)d_in[10];
    const float* bout = (const float*)d_in[11];
    float* out = (float*)d_out;

    cudaFuncSetAttribute(rnn_kernel, cudaFuncAttributeMaxDynamicSharedMemorySize,
                         SMEM_BYTES);
    rnn_kernel<<<BB / MROWS, THREADS, SMEM_BYTES>>>(
        x, hs, Wih0, Whh0, bih0, bhh0, Wih1, Whh1, bih1, bhh1, Wout, bout, out);
}

// round 12
// speedup vs baseline: 1.6811x; 1.2983x over previous
#include <cuda_runtime.h>
#include <cuda_fp16.h>

typedef unsigned int u32;

#define BB 8192
#define TT 140
#define MROWS 64
#define THREADS 512

// smem byte offsets
// weights (fp16 hi only): 3 chunks x 8192B: W0 W1i W1h
#define OFF_W    0
// h0: [parity][hi/lo] = 4 x 8192B ; h1 same  (fp16 hi/lo split)
#define OFF_H0   24576
#define OFF_H1   (24576 + 32768)
#define OFF_YP   (OFF_H1 + 32768)
#define SMEM_BYTES (OFF_YP + 512)

__device__ __forceinline__ u32 s2u(const void* p) {
    u32 a;
    asm("{ .reg .u64 t; cvta.to.shared.u64 t, %1; cvt.u32.u64 %0, t; }"
        : "=r"(a) : "l"(p));
    return a;
}
#define LDSM4(r0, r1, r2, r3, a)                                          \
    asm volatile("ldmatrix.sync.aligned.m8n8.x4.shared.b16 "              \
                 "{%0,%1,%2,%3}, [%4];"                                   \
                 : "=r"(r0), "=r"(r1), "=r"(r2), "=r"(r3) : "r"(a))

__device__ __forceinline__ void mma16816(float (&d)[4], u32 a0, u32 a1,
                                         u32 a2, u32 a3, u32 b0, u32 b1) {
    asm volatile(
        "mma.sync.aligned.m16n8k16.row.col.f32.f16.f16.f32 "
        "{%0,%1,%2,%3}, {%4,%5,%6,%7}, {%8,%9}, {%0,%1,%2,%3};"
        : "+f"(d[0]), "+f"(d[1]), "+f"(d[2]), "+f"(d[3])
        : "r"(a0), "r"(a1), "r"(a2), "r"(a3), "r"(b0), "r"(b1));
}
__device__ __forceinline__ u32 cvtpack16(float hi, float lo) {  // {lo, hi} f16x2
    u32 r;
    asm("cvt.rn.f16x2.f32 %0, %1, %2;" : "=r"(r) : "f"(hi), "f"(lo));
    return r;
}
__device__ __forceinline__ void unpack16(u32 v, float& lo, float& hi) {
    asm("{ .reg .b16 l, h; mov.b32 {l, h}, %2;\n\t"
        "cvt.f32.f16 %0, l; cvt.f32.f16 %1, h; }"
        : "=f"(lo), "=f"(hi) : "r"(v));
}
__device__ __forceinline__ float fast_tanh(float x) {
    float e = __expf(2.0f * x);
    return 1.0f - __fdividef(2.0f, e + 1.0f);
}
#define PAIRBAR(id) asm volatile("bar.sync %0, %1;" :: "r"(id), "r"(128) : "memory")
#define CONSBAR(id) asm volatile("bar.sync %0, %1;" :: "r"(id), "r"(64) : "memory")

__global__ void __launch_bounds__(THREADS, 1) rnn_kernel(
    const float* __restrict__ x, const float* __restrict__ h_state,
    const float* __restrict__ Wih0, const float* __restrict__ Whh0,
    const float* __restrict__ bih0, const float* __restrict__ bhh0,
    const float* __restrict__ Wih1, const float* __restrict__ Whh1,
    const float* __restrict__ bih1, const float* __restrict__ bhh1,
    const float* __restrict__ Wout, const float* __restrict__ bout,
    float* __restrict__ out) {
    extern __shared__ char smem[];
    const int tid  = threadIdx.x;
    const int lane = tid & 31;
    const int w    = tid >> 5;
    const int role = w >> 3;            // 0 = producer (layer 0), 1 = consumer (layer 1)
    const int hf   = (w >> 2) & 1;      // j-column half
    const int wi   = (role == 0) ? (w & 3) : ((w + 3) & 3);
    const int g    = lane >> 2;
    const int tg   = lane & 3;
    const int wr0  = wi * 16;
    const int row0 = blockIdx.x * MROWS;
    const int bidP = 1 + wi;
    const int bidC = 5 + wi;

    // ---- prologue: weights -> fp16, SW128-swizzled [j][k] ----
    {
        const float* Ws[3] = {Whh0, Wih1, Whh1};
        for (int idx = tid; idx < 3 * 4096; idx += THREADS) {
            int m = idx >> 12, e = idx & 4095, j = e >> 6, k = e & 63;
            float v = Ws[m][j * 64 + k];
            int sw = j * 128 + ((k * 2) ^ ((j & 7) << 4));
            *(__half*)(smem + OFF_W + m * 8192 + sw) = __float2half_rn(v);
        }
    }
    // h_state -> parity-0 buffers (fp16 hi/lo)
    for (int idx = tid; idx < MROWS * 64; idx += THREADS) {
        int r = idx >> 6, k = idx & 63;
        int sw = r * 128 + ((k * 2) ^ ((r & 7) << 4));
        float v0 = h_state[(row0 + r) * 64 + k];
        float v1 = h_state[BB * 64 + (row0 + r) * 64 + k];
        __half h0h = __float2half_rn(v0);
        __half h1h = __float2half_rn(v1);
        *(__half*)(smem + OFF_H0 + sw)        = h0h;
        *(__half*)(smem + OFF_H0 + 8192 + sw) = __float2half_rn(v0 - __half2float(h0h));
        *(__half*)(smem + OFF_H1 + sw)        = h1h;
        *(__half*)(smem + OFF_H1 + 8192 + sw) = __float2half_rn(v1 - __half2float(h1h));
    }
    // per-lane constants: cols j = hf*32 + nt*8 + tg*2, +1
    float2 wi2[4], b02[4], b12[4], wo2[4];
#pragma unroll
    for (int nt = 0; nt < 4; ++nt) {
        int j = hf * 32 + nt * 8 + tg * 2;
        wi2[nt] = make_float2(Wih0[j], Wih0[j + 1]);
        b02[nt] = make_float2(bih0[j] + bhh0[j], bih0[j + 1] + bhh0[j + 1]);
        b12[nt] = make_float2(bih1[j] + bhh1[j], bih1[j + 1] + bhh1[j + 1]);
        wo2[nt] = make_float2(Wout[j], Wout[j + 1]);
    }
    const float bo = bout[0];
    __syncthreads();

    const u32 smu = s2u(smem);
    const int q    = lane >> 3;
    const int arow = wr0 + ((q & 1) << 3) + (lane & 7);
    const u32 aco  = (u32)((q >> 1) << 4);
    const u32 swz  = (u32)((lane & 7) << 4);
    const u32 ab0  = smu + OFF_H0 + arow * 128;   // + parity*16384 (+8192 for lo)
    const u32 ab1  = smu + OFF_H1 + arow * 128;
    const int brl  = (((lane >> 4) & 1) << 3) + (lane & 7);
    const u32 bco  = (u32)(((lane >> 3) & 1) << 4);
    const u32 bbase = smu + OFF_W + brl * 128;
    u32 st0[4], st1[4];
#pragma unroll
    for (int nt = 0; nt < 4; ++nt) {
        u32 c = (u32)((hf * 64 + nt * 16 + tg * 4) ^ (g << 4));
        st0[nt] = smu + OFF_H0 + (wr0 + g) * 128 + c;
        st1[nt] = smu + OFF_H1 + (wr0 + g) * 128 + c;
    }
    float* yprt = (float*)(smem + OFF_YP) + wi * 32;

    if (role == 0) {
        // ================= producer: layer 0, j-half hf =================
        const float* gxA = x + (row0 + wr0 + g) * TT;
        const float* gxB = gxA + 8 * TT;
        float xAn = gxA[0], xBn = gxB[0];
        u32 p = 0;
        for (int t = 0; t < TT; ++t) {
            const u32 rdo = p * 16384u, wro = rdo ^ 16384u;
            float xA = xAn, xB = xBn;
            int tn = (t + 1 < TT) ? t + 1 : TT - 1;
            xAn = gxA[tn]; xBn = gxB[tn];

            float acc[4][4];
#pragma unroll
            for (int n = 0; n < 4; ++n)
#pragma unroll
                for (int i = 0; i < 4; ++i) acc[n][i] = 0.0f;
#pragma unroll
            for (int kt = 0; kt < 4; ++kt) {
                u32 kc = (u32)(kt << 5);
                u32 aoff = (kc | aco) ^ swz;
                u32 aH0, aH1, aH2, aH3, aL0, aL1, aL2, aL3;
                LDSM4(aH0, aH1, aH2, aH3, ab0 + rdo + aoff);
                LDSM4(aL0, aL1, aL2, aL3, ab0 + rdo + 8192 + aoff);
                u32 boff = (kc | bco) ^ swz;
#pragma unroll
                for (int np = 0; np < 2; ++np) {
                    u32 bb = bbase + (u32)((hf * 2 + np) * 2048) + boff;
                    u32 h0, h1, h2, h3;
                    LDSM4(h0, h1, h2, h3, bb);            // W0 (fp16)
                    mma16816(acc[2 * np],     aH0, aH1, aH2, aH3, h0, h1);
                    mma16816(acc[2 * np + 1], aH0, aH1, aH2, aH3, h2, h3);
                    mma16816(acc[2 * np],     aL0, aL1, aL2, aL3, h0, h1);
                    mma16816(acc[2 * np + 1], aL0, aL1, aL2, aL3, h2, h3);
                }
            }
            u32 hpA[4], lpA[4], hpB[4], lpB[4];
#pragma unroll
            for (int nt = 0; nt < 4; ++nt) {
                float vA0 = fast_tanh(acc[nt][0] + fmaf(xA, wi2[nt].x, b02[nt].x));
                float vA1 = fast_tanh(acc[nt][1] + fmaf(xA, wi2[nt].y, b02[nt].y));
                float vB0 = fast_tanh(acc[nt][2] + fmaf(xB, wi2[nt].x, b02[nt].x));
                float vB1 = fast_tanh(acc[nt][3] + fmaf(xB, wi2[nt].y, b02[nt].y));
                u32 hA = cvtpack16(vA1, vA0), hB = cvtpack16(vB1, vB0);
                float aLo, aHi, bLo, bHi;
                unpack16(hA, aLo, aHi);
                unpack16(hB, bLo, bHi);
                hpA[nt] = hA; hpB[nt] = hB;
                lpA[nt] = cvtpack16(vA1 - aHi, vA0 - aLo);
                lpB[nt] = cvtpack16(vB1 - bHi, vB0 - bLo);
            }
#pragma unroll
            for (int nt = 0; nt < 4; ++nt) {
                asm volatile("st.shared.b32 [%0], %1;" :: "r"(st0[nt] + wro), "r"(hpA[nt]));
                asm volatile("st.shared.b32 [%0], %1;" :: "r"(st0[nt] + wro + 1024), "r"(hpB[nt]));
                asm volatile("st.shared.b32 [%0], %1;" :: "r"(st0[nt] + wro + 8192), "r"(lpA[nt]));
                asm volatile("st.shared.b32 [%0], %1;" :: "r"(st0[nt] + wro + 8192 + 1024), "r"(lpB[nt]));
            }
            PAIRBAR(bidP);   // publish h0n(t) to pair
            p ^= 1;
        }
    } else {
        // ================= consumer: layer 1, j-half hf =================
        float* outy = out + (row0 + wr0 + g) * TT;
        u32 p = 0;
        for (int t = 0; t < TT; ++t) {
            const u32 rdo = p * 16384u, wro = rdo ^ 16384u;
            float acc[4][4];
#pragma unroll
            for (int n = 0; n < 4; ++n)
#pragma unroll
                for (int i = 0; i < 4; ++i) acc[n][i] = 0.0f;
            // part 1 (pre-pair-barrier): Whh1 x h1(t-1)
#pragma unroll
            for (int kt = 0; kt < 4; ++kt) {
                u32 kc = (u32)(kt << 5);
                u32 aoff = (kc | aco) ^ swz;
                u32 r0, r1, r2, r3, s0, s1, s2, s3;
                LDSM4(r0, r1, r2, r3, ab1 + rdo + aoff);
                LDSM4(s0, s1, s2, s3, ab1 + rdo + 8192 + aoff);
                u32 boff = (kc | bco) ^ swz;
#pragma unroll
                for (int np = 0; np < 2; ++np) {
                    u32 bb = bbase + (u32)((hf * 2 + np) * 2048) + boff;
                    u32 hh0, hh1, hh2, hh3;
                    LDSM4(hh0, hh1, hh2, hh3, bb + 16384);   // W1h (fp16)
                    mma16816(acc[2 * np],     r0, r1, r2, r3, hh0, hh1);
                    mma16816(acc[2 * np + 1], r0, r1, r2, r3, hh2, hh3);
                    mma16816(acc[2 * np],     s0, s1, s2, s3, hh0, hh1);
                    mma16816(acc[2 * np + 1], s0, s1, s2, s3, hh2, hh3);
                }
            }
            PAIRBAR(bidP);   // wait for producers' h0n(t)
            // part 2: Wih1 x h0n(t)  (h0n lives at parity wro)
#pragma unroll
            for (int kt = 0; kt < 4; ++kt) {
                u32 kc = (u32)(kt << 5);
                u32 aoff = (kc | aco) ^ swz;
                u32 p0, p1, p2, p3, q0, q1, q2, q3;
                LDSM4(p0, p1, p2, p3, ab0 + wro + aoff);
                LDSM4(q0, q1, q2, q3, ab0 + wro + 8192 + aoff);
                u32 boff = (kc | bco) ^ swz;
#pragma unroll
                for (int np = 0; np < 2; ++np) {
                    u32 bb = bbase + (u32)((hf * 2 + np) * 2048) + boff;
                    u32 ih0, ih1, ih2, ih3;
                    LDSM4(ih0, ih1, ih2, ih3, bb + 8192);    // W1i (fp16)
                    mma16816(acc[2 * np],     p0, p1, p2, p3, ih0, ih1);
                    mma16816(acc[2 * np + 1], p0, p1, p2, p3, ih2, ih3);
                    mma16816(acc[2 * np],     q0, q1, q2, q3, ih0, ih1);
                    mma16816(acc[2 * np + 1], q0, q1, q2, q3, ih2, ih3);
                }
            }
            float ypA = 0.0f, ypB = 0.0f;
            u32 hpA[4], lpA[4], hpB[4], lpB[4];
#pragma unroll
            for (int nt = 0; nt < 4; ++nt) {
                float vA0 = fast_tanh(acc[nt][0] + b12[nt].x);
                float vA1 = fast_tanh(acc[nt][1] + b12[nt].y);
                float vB0 = fast_tanh(acc[nt][2] + b12[nt].x);
                float vB1 = fast_tanh(acc[nt][3] + b12[nt].y);
                ypA = fmaf(vA0, wo2[nt].x, ypA); ypA = fmaf(vA1, wo2[nt].y, ypA);
                ypB = fmaf(vB0, wo2[nt].x, ypB); ypB = fmaf(vB1, wo2[nt].y, ypB);
                u32 hA = cvtpack16(vA1, vA0), hB = cvtpack16(vB1, vB0);
                float aLo, aHi, bLo, bHi;
                unpack16(hA, aLo, aHi);
                unpack16(hB, bLo, bHi);
                hpA[nt] = hA; hpB[nt] = hB;
                lpA[nt] = cvtpack16(vA1 - aHi, vA0 - aLo);
                lpB[nt] = cvtpack16(vB1 - bHi, vB0 - bLo);
            }
#pragma unroll
            for (int nt = 0; nt < 4; ++nt) {
                asm volatile("st.shared.b32 [%0], %1;" :: "r"(st1[nt] + wro), "r"(hpA[nt]));
                asm volatile("st.shared.b32 [%0], %1;" :: "r"(st1[nt] + wro + 1024), "r"(hpB[nt]));
                asm volatile("st.shared.b32 [%0], %1;" :: "r"(st1[nt] + wro + 8192), "r"(lpA[nt]));
                asm volatile("st.shared.b32 [%0], %1;" :: "r"(st1[nt] + wro + 8192 + 1024), "r"(lpB[nt]));
            }
            // y partial: reduce over tg within warp, stash per half
            ypA += __shfl_xor_sync(0xFFFFFFFF, ypA, 1);
            ypA += __shfl_xor_sync(0xFFFFFFFF, ypA, 2);
            ypB += __shfl_xor_sync(0xFFFFFFFF, ypB, 1);
            ypB += __shfl_xor_sync(0xFFFFFFFF, ypB, 2);
            if (tg == 0) {
                yprt[hf * 16 + g]     = ypA;
                yprt[hf * 16 + g + 8] = ypB;
            }
            CONSBAR(bidC);   // h1n (both halves) + ypart visible to consumer pair
            if (hf == 0 && tg == 0) {
                outy[t]          = yprt[g]     + yprt[16 + g]     + bo;
                outy[8 * TT + t] = yprt[g + 8] + yprt[16 + g + 8] + bo;
            }
            p ^= 1;
        }
    }
    __syncthreads();

    // ---- h_final from hi+lo (final state in parity 0: TT even) ----
    const int BT = BB * TT;
    for (int idx = tid; idx < MROWS * 64; idx += THREADS) {
        int r = idx >> 6, k = idx & 63;
        int sw = r * 128 + ((k * 2) ^ ((r & 7) << 4));
        float h0 = __half2float(*(__half*)(smem + OFF_H0 + sw)) +
                   __half2float(*(__half*)(smem + OFF_H0 + 8192 + sw));
        float h1 = __half2float(*(__half*)(smem + OFF_H1 + sw)) +
                   __half2float(*(__half*)(smem + OFF_H1 + 8192 + sw));
        out[BT + (row0 + r) * 64 + k]           = h0;
        out[BT + BB * 64 + (row0 + r) * 64 + k] = h1;
    }
}

extern "C" void kernel_launch(void* const* d_in, const int* in_sizes, int n_in,
                              void* d_out, int out_size) {
    (void)in_sizes; (void)n_in; (void)out_size;
    const float* x    = (const float*)d_in[0];
    const float* hs   = (const float*)d_in[1];
    const float* Wih0 = (const float*)d_in[2];
    const float* Whh0 = (const float*)d_in[3];
    const float* bih0 = (const float*)d_in[4];
    const float* bhh0 = (const float*)d_in[5];
    const float* Wih1 = (const float*)d_in[6];
    const float* Whh1 = (const float*)d_in[7];
    const float* bih1 = (const float*)d_in[8];
    const float* bhh1 = (const float*)d_in[9];
    const float* Wout = (const float*)d_in[10];
    const float* bout = (const float*)d_in[11];
    float* out = (float*)d_out;

    cudaFuncSetAttribute(rnn_kernel, cudaFuncAttributeMaxDynamicSharedMemorySize,
                         SMEM_BYTES);
    rnn_kernel<<<BB / MROWS, THREADS, SMEM_BYTES>>>(
        x, hs, Wih0, Whh0, bih0, bhh0, Wih1, Whh1, bih1, bhh1, Wout, bout, out);
}

// round 13
// speedup vs baseline: 2.3069x; 1.3722x over previous
#include <cuda_runtime.h>
#include <cuda_fp16.h>

typedef unsigned int u32;

#define BB 8192
#define TT 140
#define MROWS 64
#define THREADS 512

// smem byte offsets
// weights (fp16): 3 chunks x 8192B: W0 W1i W1h
#define OFF_W    0
// h0: [parity] = 2 x 8192B (fp16, no lo term) ; h1 same
#define OFF_H0   24576
#define OFF_H1   (24576 + 16384)
#define OFF_YP   (OFF_H1 + 16384)
#define SMEM_BYTES (OFF_YP + 512)

__device__ __forceinline__ u32 s2u(const void* p) {
    u32 a;
    asm("{ .reg .u64 t; cvta.to.shared.u64 t, %1; cvt.u32.u64 %0, t; }"
        : "=r"(a) : "l"(p));
    return a;
}
#define LDSM4(r0, r1, r2, r3, a)                                          \
    asm volatile("ldmatrix.sync.aligned.m8n8.x4.shared.b16 "              \
                 "{%0,%1,%2,%3}, [%4];"                                   \
                 : "=r"(r0), "=r"(r1), "=r"(r2), "=r"(r3) : "r"(a))

__device__ __forceinline__ void mma16816(float (&d)[4], u32 a0, u32 a1,
                                         u32 a2, u32 a3, u32 b0, u32 b1) {
    asm volatile(
        "mma.sync.aligned.m16n8k16.row.col.f32.f16.f16.f32 "
        "{%0,%1,%2,%3}, {%4,%5,%6,%7}, {%8,%9}, {%0,%1,%2,%3};"
        : "+f"(d[0]), "+f"(d[1]), "+f"(d[2]), "+f"(d[3])
        : "r"(a0), "r"(a1), "r"(a2), "r"(a3), "r"(b0), "r"(b1));
}
__device__ __forceinline__ u32 cvtpack16(float hi, float lo) {  // {lo, hi} f16x2
    u32 r;
    asm("cvt.rn.f16x2.f32 %0, %1, %2;" : "=r"(r) : "f"(hi), "f"(lo));
    return r;
}
__device__ __forceinline__ float fast_tanh(float x) {
    float e = __expf(2.0f * x);
    return 1.0f - __fdividef(2.0f, e + 1.0f);
}
#define PAIRBAR(id) asm volatile("bar.sync %0, %1;" :: "r"(id), "r"(128) : "memory")
#define CONSBAR(id) asm volatile("bar.sync %0, %1;" :: "r"(id), "r"(64) : "memory")

__global__ void __launch_bounds__(THREADS, 1) rnn_kernel(
    const float* __restrict__ x, const float* __restrict__ h_state,
    const float* __restrict__ Wih0, const float* __restrict__ Whh0,
    const float* __restrict__ bih0, const float* __restrict__ bhh0,
    const float* __restrict__ Wih1, const float* __restrict__ Whh1,
    const float* __restrict__ bih1, const float* __restrict__ bhh1,
    const float* __restrict__ Wout, const float* __restrict__ bout,
    float* __restrict__ out) {
    extern __shared__ char smem[];
    const int tid  = threadIdx.x;
    const int lane = tid & 31;
    const int w    = tid >> 5;
    const int role = w >> 3;            // 0 = producer (layer 0), 1 = consumer (layer 1)
    const int hf   = (w >> 2) & 1;      // j-column half
    const int wi   = (role == 0) ? (w & 3) : ((w + 3) & 3);
    const int g    = lane >> 2;
    const int tg   = lane & 3;
    const int wr0  = wi * 16;
    const int row0 = blockIdx.x * MROWS;
    const int bidP = 1 + wi;
    const int bidC = 5 + wi;
    const int BT   = BB * TT;

    // ---- prologue: weights -> fp16, SW128-swizzled [j][k] ----
    {
        const float* Ws[3] = {Whh0, Wih1, Whh1};
        for (int idx = tid; idx < 3 * 4096; idx += THREADS) {
            int m = idx >> 12, e = idx & 4095, j = e >> 6, k = e & 63;
            float v = Ws[m][j * 64 + k];
            int sw = j * 128 + ((k * 2) ^ ((j & 7) << 4));
            *(__half*)(smem + OFF_W + m * 8192 + sw) = __float2half_rn(v);
        }
    }
    // h_state -> parity-0 buffers (fp16)
    for (int idx = tid; idx < MROWS * 64; idx += THREADS) {
        int r = idx >> 6, k = idx & 63;
        int sw = r * 128 + ((k * 2) ^ ((r & 7) << 4));
        *(__half*)(smem + OFF_H0 + sw) = __float2half_rn(h_state[(row0 + r) * 64 + k]);
        *(__half*)(smem + OFF_H1 + sw) = __float2half_rn(h_state[BB * 64 + (row0 + r) * 64 + k]);
    }
    // per-lane constants: cols j = hf*32 + nt*8 + tg*2, +1
    float2 wi2[4], b02[4], b12[4], wo2[4];
#pragma unroll
    for (int nt = 0; nt < 4; ++nt) {
        int j = hf * 32 + nt * 8 + tg * 2;
        wi2[nt] = make_float2(Wih0[j], Wih0[j + 1]);
        b02[nt] = make_float2(bih0[j] + bhh0[j], bih0[j + 1] + bhh0[j + 1]);
        b12[nt] = make_float2(bih1[j] + bhh1[j], bih1[j + 1] + bhh1[j + 1]);
        wo2[nt] = make_float2(Wout[j], Wout[j + 1]);
    }
    const float bo = bout[0];
    __syncthreads();

    const u32 smu = s2u(smem);
    const int q    = lane >> 3;
    const int arow = wr0 + ((q & 1) << 3) + (lane & 7);
    const u32 aco  = (u32)((q >> 1) << 4);
    const u32 swz  = (u32)((lane & 7) << 4);
    const u32 ab0  = smu + OFF_H0 + arow * 128;   // + parity*8192
    const u32 ab1  = smu + OFF_H1 + arow * 128;
    const int brl  = (((lane >> 4) & 1) << 3) + (lane & 7);
    const u32 bco  = (u32)(((lane >> 3) & 1) << 4);
    const u32 bbase = smu + OFF_W + brl * 128;
    u32 st0[4], st1[4];
#pragma unroll
    for (int nt = 0; nt < 4; ++nt) {
        u32 c = (u32)((hf * 64 + nt * 16 + tg * 4) ^ (g << 4));
        st0[nt] = smu + OFF_H0 + (wr0 + g) * 128 + c;
        st1[nt] = smu + OFF_H1 + (wr0 + g) * 128 + c;
    }
    float* yprt = (float*)(smem + OFF_YP) + wi * 32;
    // final-state fp32 output base (rows wr0+g / wr0+g+8, cols j)
    float* hf0out = out + BT + (row0 + wr0 + g) * 64 + hf * 32;
    float* hf1out = hf0out + BB * 64;

    if (role == 0) {
        // ================= producer: layer 0, j-half hf =================
        const float* gxA = x + (row0 + wr0 + g) * TT;
        const float* gxB = gxA + 8 * TT;
        float xAn = gxA[0], xBn = gxB[0];
        u32 p = 0;
        for (int t = 0; t < TT; ++t) {
            const u32 rdo = p * 8192u, wro = rdo ^ 8192u;
            float xA = xAn, xB = xBn;
            int tn = (t + 1 < TT) ? t + 1 : TT - 1;
            xAn = gxA[tn]; xBn = gxB[tn];

            float acc[4][4];
#pragma unroll
            for (int n = 0; n < 4; ++n)
#pragma unroll
                for (int i = 0; i < 4; ++i) acc[n][i] = 0.0f;
#pragma unroll
            for (int kt = 0; kt < 4; ++kt) {
                u32 kc = (u32)(kt << 5);
                u32 aoff = (kc | aco) ^ swz;
                u32 aH0, aH1, aH2, aH3;
                LDSM4(aH0, aH1, aH2, aH3, ab0 + rdo + aoff);
                u32 boff = (kc | bco) ^ swz;
#pragma unroll
                for (int np = 0; np < 2; ++np) {
                    u32 bb = bbase + (u32)((hf * 2 + np) * 2048) + boff;
                    u32 h0, h1, h2, h3;
                    LDSM4(h0, h1, h2, h3, bb);            // W0 (fp16)
                    mma16816(acc[2 * np],     aH0, aH1, aH2, aH3, h0, h1);
                    mma16816(acc[2 * np + 1], aH0, aH1, aH2, aH3, h2, h3);
                }
            }
            u32 hpA[4], hpB[4];
            float fvA[8], fvB[8];
#pragma unroll
            for (int nt = 0; nt < 4; ++nt) {
                float vA0 = fast_tanh(acc[nt][0] + fmaf(xA, wi2[nt].x, b02[nt].x));
                float vA1 = fast_tanh(acc[nt][1] + fmaf(xA, wi2[nt].y, b02[nt].y));
                float vB0 = fast_tanh(acc[nt][2] + fmaf(xB, wi2[nt].x, b02[nt].x));
                float vB1 = fast_tanh(acc[nt][3] + fmaf(xB, wi2[nt].y, b02[nt].y));
                hpA[nt] = cvtpack16(vA1, vA0);
                hpB[nt] = cvtpack16(vB1, vB0);
                fvA[2 * nt] = vA0; fvA[2 * nt + 1] = vA1;
                fvB[2 * nt] = vB0; fvB[2 * nt + 1] = vB1;
            }
#pragma unroll
            for (int nt = 0; nt < 4; ++nt) {
                asm volatile("st.shared.b32 [%0], %1;" :: "r"(st0[nt] + wro), "r"(hpA[nt]));
                asm volatile("st.shared.b32 [%0], %1;" :: "r"(st0[nt] + wro + 1024), "r"(hpB[nt]));
            }
            if (t == TT - 1) {   // fp32 h0 final
#pragma unroll
                for (int nt = 0; nt < 4; ++nt) {
                    int j = nt * 8 + tg * 2;
                    hf0out[j]            = fvA[2 * nt];
                    hf0out[j + 1]        = fvA[2 * nt + 1];
                    hf0out[8 * 64 + j]     = fvB[2 * nt];
                    hf0out[8 * 64 + j + 1] = fvB[2 * nt + 1];
                }
            }
            PAIRBAR(bidP);   // publish h0n(t) to pair
            p ^= 1;
        }
    } else {
        // ================= consumer: layer 1, j-half hf =================
        float* outy = out + (row0 + wr0 + g) * TT;
        u32 p = 0;
        for (int t = 0; t < TT; ++t) {
            const u32 rdo = p * 8192u, wro = rdo ^ 8192u;
            float acc[4][4];
#pragma unroll
            for (int n = 0; n < 4; ++n)
#pragma unroll
                for (int i = 0; i < 4; ++i) acc[n][i] = 0.0f;
            // part 1 (pre-pair-barrier): Whh1 x h1(t-1)
#pragma unroll
            for (int kt = 0; kt < 4; ++kt) {
                u32 kc = (u32)(kt << 5);
                u32 aoff = (kc | aco) ^ swz;
                u32 r0, r1, r2, r3;
                LDSM4(r0, r1, r2, r3, ab1 + rdo + aoff);
                u32 boff = (kc | bco) ^ swz;
#pragma unroll
                for (int np = 0; np < 2; ++np) {
                    u32 bb = bbase + (u32)((hf * 2 + np) * 2048) + boff;
                    u32 hh0, hh1, hh2, hh3;
                    LDSM4(hh0, hh1, hh2, hh3, bb + 16384);   // W1h (fp16)
                    mma16816(acc[2 * np],     r0, r1, r2, r3, hh0, hh1);
                    mma16816(acc[2 * np + 1], r0, r1, r2, r3, hh2, hh3);
                }
            }
            PAIRBAR(bidP);   // wait for producers' h0n(t)
            // part 2: Wih1 x h0n(t)  (h0n lives at parity wro)
#pragma unroll
            for (int kt = 0; kt < 4; ++kt) {
                u32 kc = (u32)(kt << 5);
                u32 aoff = (kc | aco) ^ swz;
                u32 p0, p1, p2, p3;
                LDSM4(p0, p1, p2, p3, ab0 + wro + aoff);
                u32 boff = (kc | bco) ^ swz;
#pragma unroll
                for (int np = 0; np < 2; ++np) {
                    u32 bb = bbase + (u32)((hf * 2 + np) * 2048) + boff;
                    u32 ih0, ih1, ih2, ih3;
                    LDSM4(ih0, ih1, ih2, ih3, bb + 8192);    // W1i (fp16)
                    mma16816(acc[2 * np],     p0, p1, p2, p3, ih0, ih1);
                    mma16816(acc[2 * np + 1], p0, p1, p2, p3, ih2, ih3);
                }
            }
            float ypA = 0.0f, ypB = 0.0f;
            u32 hpA[4], hpB[4];
            float fvA[8], fvB[8];
#pragma unroll
            for (int nt = 0; nt < 4; ++nt) {
                float vA0 = fast_tanh(acc[nt][0] + b12[nt].x);
                float vA1 = fast_tanh(acc[nt][1] + b12[nt].y);
                float vB0 = fast_tanh(acc[nt][2] + b12[nt].x);
                float vB1 = fast_tanh(acc[nt][3] + b12[nt].y);
                ypA = fmaf(vA0, wo2[nt].x, ypA); ypA = fmaf(vA1, wo2[nt].y, ypA);
                ypB = fmaf(vB0, wo2[nt].x, ypB); ypB = fmaf(vB1, wo2[nt].y, ypB);
                hpA[nt] = cvtpack16(vA1, vA0);
                hpB[nt] = cvtpack16(vB1, vB0);
                fvA[2 * nt] = vA0; fvA[2 * nt + 1] = vA1;
                fvB[2 * nt] = vB0; fvB[2 * nt + 1] = vB1;
            }
#pragma unroll
            for (int nt = 0; nt < 4; ++nt) {
                asm volatile("st.shared.b32 [%0], %1;" :: "r"(st1[nt] + wro), "r"(hpA[nt]));
                asm volatile("st.shared.b32 [%0], %1;" :: "r"(st1[nt] + wro + 1024), "r"(hpB[nt]));
            }
            if (t == TT - 1) {   // fp32 h1 final
#pragma unroll
                for (int nt = 0; nt < 4; ++nt) {
                    int j = nt * 8 + tg * 2;
                    hf1out[j]            = fvA[2 * nt];
                    hf1out[j + 1]        = fvA[2 * nt + 1];
                    hf1out[8 * 64 + j]     = fvB[2 * nt];
                    hf1out[8 * 64 + j + 1] = fvB[2 * nt + 1];
                }
            }
            // y partial: reduce over tg within warp, stash per half
            ypA += __shfl_xor_sync(0xFFFFFFFF, ypA, 1);
            ypA += __shfl_xor_sync(0xFFFFFFFF, ypA, 2);
            ypB += __shfl_xor_sync(0xFFFFFFFF, ypB, 1);
            ypB += __shfl_xor_sync(0xFFFFFFFF, ypB, 2);
            if (tg == 0) {
                yprt[hf * 16 + g]     = ypA;
                yprt[hf * 16 + g + 8] = ypB;
            }
            CONSBAR(bidC);   // h1n (both halves) + ypart visible to consumer pair
            if (hf == 0 && tg == 0) {
                outy[t]          = yprt[g]     + yprt[16 + g]     + bo;
                outy[8 * TT + t] = yprt[g + 8] + yprt[16 + g + 8] + bo;
            }
            p ^= 1;
        }
    }
}

extern "C" void kernel_launch(void* const* d_in, const int* in_sizes, int n_in,
                              void* d_out, int out_size) {
    (void)in_sizes; (void)n_in; (void)out_size;
    const float* x    = (const float*)d_in[0];
    const float* hs   = (const float*)d_in[1];
    const float* Wih0 = (const float*)d_in[2];
    const float* Whh0 = (const float*)d_in[3];
    const float* bih0 = (const float*)d_in[4];
    const float* bhh0 = (const float*)d_in[5];
    const float* Wih1 = (const float*)d_in[6];
    const float* Whh1 = (const float*)d_in[7];
    const float* bih1 = (const float*)d_in[8];
    const float* bhh1 = (const float*)d_in[9];
    const float* Wout = (const float*)d_in[10];
    const float* bout = (const float*)d_in[11];
    float* out = (float*)d_out;

    cudaFuncSetAttribute(rnn_kernel, cudaFuncAttributeMaxDynamicSharedMemorySize,
                         SMEM_BYTES);
    rnn_kernel<<<BB / MROWS, THREADS, SMEM_BYTES>>>(
        x, hs, Wih0, Whh0, bih0, bhh0, Wih1, Whh1, bih1, bhh1, Wout, bout, out);
}

// round 14
// speedup vs baseline: 2.3361x; 1.0127x over previous
#include <cuda_runtime.h>
#include <cuda_fp16.h>

typedef unsigned int u32;

#define BB 8192
#define TT 140
#define MROWS 64
#define THREADS 512

// smem byte offsets
// weights (fp16): 3 chunks x 8192B: W0 W1i W1h
#define OFF_W    0
// h0: [parity] = 2 x 8192B (fp16) ; h1 same
#define OFF_H0   24576
#define OFF_H1   (24576 + 16384)
#define OFF_YP   (OFF_H1 + 16384)
#define SMEM_BYTES (OFF_YP + 512)

__device__ __forceinline__ u32 s2u(const void* p) {
    u32 a;
    asm("{ .reg .u64 t; cvta.to.shared.u64 t, %1; cvt.u32.u64 %0, t; }"
        : "=r"(a) : "l"(p));
    return a;
}
#define LDSM4(r0, r1, r2, r3, a)                                          \
    asm volatile("ldmatrix.sync.aligned.m8n8.x4.shared.b16 "              \
                 "{%0,%1,%2,%3}, [%4];"                                   \
                 : "=r"(r0), "=r"(r1), "=r"(r2), "=r"(r3) : "r"(a))

__device__ __forceinline__ void mma16816(float (&d)[4], u32 a0, u32 a1,
                                         u32 a2, u32 a3, u32 b0, u32 b1) {
    asm volatile(
        "mma.sync.aligned.m16n8k16.row.col.f32.f16.f16.f32 "
        "{%0,%1,%2,%3}, {%4,%5,%6,%7}, {%8,%9}, {%0,%1,%2,%3};"
        : "+f"(d[0]), "+f"(d[1]), "+f"(d[2]), "+f"(d[3])
        : "r"(a0), "r"(a1), "r"(a2), "r"(a3), "r"(b0), "r"(b1));
}
__device__ __forceinline__ u32 cvtpack16(float hi, float lo) {  // {lo, hi} f16x2
    u32 r;
    asm("cvt.rn.f16x2.f32 %0, %1, %2;" : "=r"(r) : "f"(hi), "f"(lo));
    return r;
}
__device__ __forceinline__ float fast_tanh(float x) {
    float e = __expf(2.0f * x);
    return 1.0f - __fdividef(2.0f, e + 1.0f);
}
#define PAIRBAR(id) asm volatile("bar.sync %0, %1;" :: "r"(id), "r"(128) : "memory")
#define CONSBAR(id) asm volatile("bar.sync %0, %1;" :: "r"(id), "r"(64) : "memory")

__global__ void __launch_bounds__(THREADS, 1) rnn_kernel(
    const float* __restrict__ x, const float* __restrict__ h_state,
    const float* __restrict__ Wih0, const float* __restrict__ Whh0,
    const float* __restrict__ bih0, const float* __restrict__ bhh0,
    const float* __restrict__ Wih1, const float* __restrict__ Whh1,
    const float* __restrict__ bih1, const float* __restrict__ bhh1,
    const float* __restrict__ Wout, const float* __restrict__ bout,
    float* __restrict__ out) {
    extern __shared__ char smem[];
    const int tid  = threadIdx.x;
    const int lane = tid & 31;
    const int w    = tid >> 5;
    const int role = w >> 3;            // 0 = producer (layer 0), 1 = consumer (layer 1)
    const int hf   = (w >> 2) & 1;      // j-column half
    const int wi   = (role == 0) ? (w & 3) : ((w + 3) & 3);
    const int g    = lane >> 2;
    const int tg   = lane & 3;
    const int wr0  = wi * 16;
    const int row0 = blockIdx.x * MROWS;
    const int bidP = 1 + wi;
    const int bidC = 5 + wi;
    const int BT   = BB * TT;

    // ---- prologue: weights -> fp16, SW128-swizzled [j][k] ----
    {
        const float* Ws[3] = {Whh0, Wih1, Whh1};
        for (int idx = tid; idx < 3 * 4096; idx += THREADS) {
            int m = idx >> 12, e = idx & 4095, j = e >> 6, k = e & 63;
            float v = Ws[m][j * 64 + k];
            int sw = j * 128 + ((k * 2) ^ ((j & 7) << 4));
            *(__half*)(smem + OFF_W + m * 8192 + sw) = __float2half_rn(v);
        }
    }
    // h_state -> parity-0 buffers (fp16)
    for (int idx = tid; idx < MROWS * 64; idx += THREADS) {
        int r = idx >> 6, k = idx & 63;
        int sw = r * 128 + ((k * 2) ^ ((r & 7) << 4));
        *(__half*)(smem + OFF_H0 + sw) = __float2half_rn(h_state[(row0 + r) * 64 + k]);
        *(__half*)(smem + OFF_H1 + sw) = __float2half_rn(h_state[BB * 64 + (row0 + r) * 64 + k]);
    }
    // per-lane constants: cols j = hf*32 + nt*8 + tg*2, +1
    float2 wi2[4], b02[4], b12[4], wo2[4];
#pragma unroll
    for (int nt = 0; nt < 4; ++nt) {
        int j = hf * 32 + nt * 8 + tg * 2;
        wi2[nt] = make_float2(Wih0[j], Wih0[j + 1]);
        b02[nt] = make_float2(bih0[j] + bhh0[j], bih0[j + 1] + bhh0[j + 1]);
        b12[nt] = make_float2(bih1[j] + bhh1[j], bih1[j + 1] + bhh1[j + 1]);
        wo2[nt] = make_float2(Wout[j], Wout[j + 1]);
    }
    const float bo = bout[0];
    __syncthreads();

    const u32 smu = s2u(smem);
    const int q    = lane >> 3;
    const int arow = wr0 + ((q & 1) << 3) + (lane & 7);
    const u32 aco  = (u32)((q >> 1) << 4);
    const u32 swz  = (u32)((lane & 7) << 4);
    const u32 ab0  = smu + OFF_H0 + arow * 128;   // + parity*8192
    const u32 ab1  = smu + OFF_H1 + arow * 128;
    const int brl  = (((lane >> 4) & 1) << 3) + (lane & 7);
    const u32 bco  = (u32)(((lane >> 3) & 1) << 4);
    const u32 bbase = smu + OFF_W + brl * 128;
    u32 st0[4], st1[4];
#pragma unroll
    for (int nt = 0; nt < 4; ++nt) {
        u32 c = (u32)((hf * 64 + nt * 16 + tg * 4) ^ (g << 4));
        st0[nt] = smu + OFF_H0 + (wr0 + g) * 128 + c;
        st1[nt] = smu + OFF_H1 + (wr0 + g) * 128 + c;
    }
    float* yprt = (float*)(smem + OFF_YP) + wi * 32;
    float* hf0out = out + BT + (row0 + wr0 + g) * 64 + hf * 32;
    float* hf1out = hf0out + BB * 64;

    if (role == 0) {
        // ================= producer: layer 0, j-half hf =================
        // hoist W0 fragments (loop-invariant) into registers
        u32 w0f[4][2][4];
#pragma unroll
        for (int kt = 0; kt < 4; ++kt) {
            u32 boff = ((u32)(kt << 5) | bco) ^ swz;
#pragma unroll
            for (int np = 0; np < 2; ++np) {
                u32 bb = bbase + (u32)((hf * 2 + np) * 2048) + boff;
                LDSM4(w0f[kt][np][0], w0f[kt][np][1], w0f[kt][np][2], w0f[kt][np][3], bb);
            }
        }
        const float* gxA = x + (row0 + wr0 + g) * TT;
        const float* gxB = gxA + 8 * TT;
        float xAn = gxA[0], xBn = gxB[0];
        u32 p = 0;
        for (int t = 0; t < TT; ++t) {
            const u32 rdo = p * 8192u, wro = rdo ^ 8192u;
            float xA = xAn, xB = xBn;
            int tn = (t + 1 < TT) ? t + 1 : TT - 1;
            xAn = gxA[tn]; xBn = gxB[tn];

            float acc[4][4];
#pragma unroll
            for (int n = 0; n < 4; ++n)
#pragma unroll
                for (int i = 0; i < 4; ++i) acc[n][i] = 0.0f;
#pragma unroll
            for (int kt = 0; kt < 4; ++kt) {
                u32 aoff = (((u32)(kt << 5)) | aco) ^ swz;
                u32 aH0, aH1, aH2, aH3;
                LDSM4(aH0, aH1, aH2, aH3, ab0 + rdo + aoff);
#pragma unroll
                for (int np = 0; np < 2; ++np) {
                    mma16816(acc[2 * np],     aH0, aH1, aH2, aH3,
                             w0f[kt][np][0], w0f[kt][np][1]);
                    mma16816(acc[2 * np + 1], aH0, aH1, aH2, aH3,
                             w0f[kt][np][2], w0f[kt][np][3]);
                }
            }
            u32 hpA[4], hpB[4];
#pragma unroll
            for (int nt = 0; nt < 4; ++nt) {
                float vA0 = fast_tanh(acc[nt][0] + fmaf(xA, wi2[nt].x, b02[nt].x));
                float vA1 = fast_tanh(acc[nt][1] + fmaf(xA, wi2[nt].y, b02[nt].y));
                float vB0 = fast_tanh(acc[nt][2] + fmaf(xB, wi2[nt].x, b02[nt].x));
                float vB1 = fast_tanh(acc[nt][3] + fmaf(xB, wi2[nt].y, b02[nt].y));
                hpA[nt] = cvtpack16(vA1, vA0);
                hpB[nt] = cvtpack16(vB1, vB0);
                if (t == TT - 1) {   // fp32 h0 final
                    int j = nt * 8 + tg * 2;
                    hf0out[j]              = vA0;
                    hf0out[j + 1]          = vA1;
                    hf0out[8 * 64 + j]     = vB0;
                    hf0out[8 * 64 + j + 1] = vB1;
                }
            }
#pragma unroll
            for (int nt = 0; nt < 4; ++nt) {
                asm volatile("st.shared.b32 [%0], %1;" :: "r"(st0[nt] + wro), "r"(hpA[nt]));
                asm volatile("st.shared.b32 [%0], %1;" :: "r"(st0[nt] + wro + 1024), "r"(hpB[nt]));
            }
            PAIRBAR(bidP);   // publish h0n(t) to pair
            p ^= 1;
        }
    } else {
        // ================= consumer: layer 1, j-half hf =================
        // hoist W1h fragments (loop-invariant) into registers
        u32 whf[4][2][4];
#pragma unroll
        for (int kt = 0; kt < 4; ++kt) {
            u32 boff = ((u32)(kt << 5) | bco) ^ swz;
#pragma unroll
            for (int np = 0; np < 2; ++np) {
                u32 bb = bbase + (u32)((hf * 2 + np) * 2048) + boff + 16384;
                LDSM4(whf[kt][np][0], whf[kt][np][1], whf[kt][np][2], whf[kt][np][3], bb);
            }
        }
        float* outy = out + (row0 + wr0 + g) * TT;
        u32 p = 0;
        for (int t = 0; t < TT; ++t) {
            const u32 rdo = p * 8192u, wro = rdo ^ 8192u;
            float acc[4][4];
#pragma unroll
            for (int n = 0; n < 4; ++n)
#pragma unroll
                for (int i = 0; i < 4; ++i) acc[n][i] = 0.0f;
            // part 1 (pre-pair-barrier): Whh1 x h1(t-1)
#pragma unroll
            for (int kt = 0; kt < 4; ++kt) {
                u32 aoff = (((u32)(kt << 5)) | aco) ^ swz;
                u32 r0, r1, r2, r3;
                LDSM4(r0, r1, r2, r3, ab1 + rdo + aoff);
#pragma unroll
                for (int np = 0; np < 2; ++np) {
                    mma16816(acc[2 * np],     r0, r1, r2, r3,
                             whf[kt][np][0], whf[kt][np][1]);
                    mma16816(acc[2 * np + 1], r0, r1, r2, r3,
                             whf[kt][np][2], whf[kt][np][3]);
                }
            }
            PAIRBAR(bidP);   // wait for producers' h0n(t)
            // part 2: Wih1 x h0n(t)  (h0n lives at parity wro)
#pragma unroll
            for (int kt = 0; kt < 4; ++kt) {
                u32 kc = (u32)(kt << 5);
                u32 aoff = (kc | aco) ^ swz;
                u32 p0, p1, p2, p3;
                LDSM4(p0, p1, p2, p3, ab0 + wro + aoff);
                u32 boff = (kc | bco) ^ swz;
#pragma unroll
                for (int np = 0; np < 2; ++np) {
                    u32 bb = bbase + (u32)((hf * 2 + np) * 2048) + boff;
                    u32 ih0, ih1, ih2, ih3;
                    LDSM4(ih0, ih1, ih2, ih3, bb + 8192);    // W1i (fp16)
                    mma16816(acc[2 * np],     p0, p1, p2, p3, ih0, ih1);
                    mma16816(acc[2 * np + 1], p0, p1, p2, p3, ih2, ih3);
                }
            }
            float ypA = 0.0f, ypB = 0.0f;
            u32 hpA[4], hpB[4];
#pragma unroll
            for (int nt = 0; nt < 4; ++nt) {
                float vA0 = fast_tanh(acc[nt][0] + b12[nt].x);
                float vA1 = fast_tanh(acc[nt][1] + b12[nt].y);
                float vB0 = fast_tanh(acc[nt][2] + b12[nt].x);
                float vB1 = fast_tanh(acc[nt][3] + b12[nt].y);
                ypA = fmaf(vA0, wo2[nt].x, ypA); ypA = fmaf(vA1, wo2[nt].y, ypA);
                ypB = fmaf(vB0, wo2[nt].x, ypB); ypB = fmaf(vB1, wo2[nt].y, ypB);
                hpA[nt] = cvtpack16(vA1, vA0);
                hpB[nt] = cvtpack16(vB1, vB0);
                if (t == TT - 1) {   // fp32 h1 final
                    int j = nt * 8 + tg * 2;
                    hf1out[j]              = vA0;
                    hf1out[j + 1]          = vA1;
                    hf1out[8 * 64 + j]     = vB0;
                    hf1out[8 * 64 + j + 1] = vB1;
                }
            }
#pragma unroll
            for (int nt = 0; nt < 4; ++nt) {
                asm volatile("st.shared.b32 [%0], %1;" :: "r"(st1[nt] + wro), "r"(hpA[nt]));
                asm volatile("st.shared.b32 [%0], %1;" :: "r"(st1[nt] + wro + 1024), "r"(hpB[nt]));
            }
            // y partial: reduce over tg within warp, stash per half
            ypA += __shfl_xor_sync(0xFFFFFFFF, ypA, 1);
            ypA += __shfl_xor_sync(0xFFFFFFFF, ypA, 2);
            ypB += __shfl_xor_sync(0xFFFFFFFF, ypB, 1);
            ypB += __shfl_xor_sync(0xFFFFFFFF, ypB, 2);
            if (tg == 0) {
                yprt[hf * 16 + g]     = ypA;
                yprt[hf * 16 + g + 8] = ypB;
            }
            CONSBAR(bidC);   // h1n (both halves) + ypart visible to consumer pair
            if (hf == 0 && tg == 0) {
                outy[t]          = yprt[g]     + yprt[16 + g]     + bo;
                outy[8 * TT + t] = yprt[g + 8] + yprt[16 + g + 8] + bo;
            }
            p ^= 1;
        }
    }
}

extern "C" void kernel_launch(void* const* d_in, const int* in_sizes, int n_in,
                              void* d_out, int out_size) {
    (void)in_sizes; (void)n_in; (void)out_size;
    const float* x    = (const float*)d_in[0];
    const float* hs   = (const float*)d_in[1];
    const float* Wih0 = (const float*)d_in[2];
    const float* Whh0 = (const float*)d_in[3];
    const float* bih0 = (const float*)d_in[4];
    const float* bhh0 = (const float*)d_in[5];
    const float* Wih1 = (const float*)d_in[6];
    const float* Whh1 = (const float*)d_in[7];
    const float* bih1 = (const float*)d_in[8];
    const float* bhh1 = (const float*)d_in[9];
    const float* Wout = (const float*)d_in[10];
    const float* bout = (const float*)d_in[11];
    float* out = (float*)d_out;

    cudaFuncSetAttribute(rnn_kernel, cudaFuncAttributeMaxDynamicSharedMemorySize,
                         SMEM_BYTES);
    rnn_kernel<<<BB / MROWS, THREADS, SMEM_BYTES>>>(
        x, hs, Wih0, Whh0, bih0, bhh0, Wih1, Whh1, bih1, bhh1, Wout, bout, out);
}